// round 2
// baseline (speedup 1.0000x reference)
#include <cuda_runtime.h>
#include <cuda_fp16.h>

// WordHashing: sparse [B=16384 x 30000] (COO, rows sorted) @ W [30000 x 300] + bias, ReLU.
// Strategy: stage W as fp16 padded rows (320 halves = 640B, 5 aligned L2 lines),
// halving gather traffic through L1tex/L2 (the round-1 bottleneck: L1=72.9%).

#define OUT_DIM   300
#define IN_DIM    30000
#define PAD_H2    160          // half2 slots per padded row (150 used + 10 pad)
#define MAX_BATCH 16384

// Scratch (allocation is forbidden in kernel_launch; __device__ globals are the sanctioned path)
__device__ int g_row_start[MAX_BATCH + 2];
__device__ __align__(128) __half2 g_Wh[IN_DIM * PAD_H2];   // 19.2 MB fp16 staged weights

// ---------------------------------------------------------------------------
// Kernel 0: convert weights f32 -> f16, padded to 640B rows.
// One thread per half2 output slot. Coalesced-ish reads, fully coalesced writes.
__global__ void convert_w(const float* __restrict__ W) {
    int i = blockIdx.x * blockDim.x + threadIdx.x;        // [0, IN_DIM*PAD_H2)
    if (i >= IN_DIM * PAD_H2) return;
    int row = i / PAD_H2;
    int k   = i - row * PAD_H2;                           // half2 index within row
    __half2 h = __float2half2_rn(0.0f);
    if (k < OUT_DIM / 2) {
        const float2 f = *reinterpret_cast<const float2*>(W + (size_t)row * OUT_DIM + 2 * k);
        h = __floats2half2_rn(f.x, f.y);
    }
    g_Wh[i] = h;
}

// ---------------------------------------------------------------------------
// Kernel 1: boundary-marking to build row_start from sorted sp_rows.
__global__ void build_row_ptr(const int* __restrict__ rows, int nnz, int batch) {
    int i = blockIdx.x * blockDim.x + threadIdx.x;
    if (i >= nnz) return;
    int r  = rows[i];
    int rp = (i == 0) ? -1 : rows[i - 1];
    for (int q = rp + 1; q <= r; ++q) g_row_start[q] = i;
    if (i == nnz - 1) {
        for (int q = r + 1; q <= batch; ++q) g_row_start[q] = nnz;
    }
}

// ---------------------------------------------------------------------------
// Kernel 2: one CTA per output row. Threads 0..149 each own 2 columns.
// Per-nnz gather: 150 lanes x half2(4B) = 600B from one aligned 640B row.
__global__ __launch_bounds__(160) void spmm_row_kernel(
    const int*   __restrict__ cols,
    const float* __restrict__ vals,
    const float* __restrict__ bias,
    float*       __restrict__ out)
{
    const int row = blockIdx.x;
    const int t   = threadIdx.x;
    if (t >= OUT_DIM / 2) return;          // no block sync used; early exit is safe

    const int start = g_row_start[row];
    const int end   = g_row_start[row + 1];

    float ax = 0.0f, ay = 0.0f;

    #pragma unroll 4
    for (int i = start; i < end; ++i) {
        const int   c = __ldg(cols + i);   // uniform -> one broadcast per warp
        const float v = __ldg(vals + i);
        const __half2 wh = g_Wh[c * PAD_H2 + t];
        const float2  wf = __half22float2(wh);
        ax = fmaf(v, wf.x, ax);
        ay = fmaf(v, wf.y, ay);
    }

    const float2 b = *reinterpret_cast<const float2*>(bias + 2 * t);
    float2 o;
    o.x = fmaxf(ax + b.x, 0.0f);
    o.y = fmaxf(ay + b.y, 0.0f);
    *reinterpret_cast<float2*>(out + (size_t)row * OUT_DIM + 2 * t) = o;
}

extern "C" void kernel_launch(void* const* d_in, const int* in_sizes, int n_in,
                              void* d_out, int out_size) {
    const int*   sp_rows = (const int*)  d_in[0];
    const int*   sp_cols = (const int*)  d_in[1];
    const float* sp_vals = (const float*)d_in[2];
    const float* weights = (const float*)d_in[3];
    const float* bias    = (const float*)d_in[4];

    const int nnz   = in_sizes[0];
    const int batch = out_size / OUT_DIM;

    const int n_conv = IN_DIM * PAD_H2;
    convert_w<<<(n_conv + 255) / 256, 256>>>(weights);
    build_row_ptr<<<(nnz + 255) / 256, 256>>>(sp_rows, nnz, batch);
    spmm_row_kernel<<<batch, 160>>>(sp_cols, sp_vals, bias, (float*)d_out);
}

// round 3
// speedup vs baseline: 1.3626x; 1.3626x over previous
#include <cuda_runtime.h>
#include <cuda_fp16.h>

// WordHashing: sparse [B=16384 x 30000] (COO, rows sorted) @ W [30000 x 300] + bias, ReLU.
// R2 post-mortem: spmm was pinned at the LDG issue floor (~15 LDG issues/nnz x 1.82cyc).
// R3: 16B gathers (2 LDG/nnz) + shuffle-batched col/val (~0.13 LDG/nnz), fp16 rows keep
// L2 traffic at 640B/nnz -> L2-BW bound ~26us.

#define OUT_DIM   300
#define IN_DIM    30000
#define ROW_INT4  40           // 40 x int4 (16B) = 640B per padded fp16 row (320 halves)
#define MAX_BATCH 16384

__device__ int g_row_start[MAX_BATCH + 2];
__device__ __align__(128) int4 g_Wh4[IN_DIM * ROW_INT4];   // 19.2 MB fp16 staged weights

// ---------------------------------------------------------------------------
// Kernel 0: W f32 -> padded f16 rows. Thread k of a row converts cols [8k, 8k+8).
// float4 reads (coalesced), int4 writes (coalesced).
__global__ void convert_w(const float* __restrict__ W) {
    const int i = blockIdx.x * blockDim.x + threadIdx.x;
    if (i >= IN_DIM * ROW_INT4) return;
    const int row = i / ROW_INT4;
    const int k   = i - row * ROW_INT4;
    const int col = k * 8;

    float4 a = make_float4(0.f, 0.f, 0.f, 0.f);
    float4 b = make_float4(0.f, 0.f, 0.f, 0.f);
    const float4* src = reinterpret_cast<const float4*>(W + (size_t)row * OUT_DIM + col);
    if (col + 8 <= OUT_DIM)      { a = src[0]; b = src[1]; }
    else if (col < OUT_DIM)      { a = src[0]; }           // col==296: cols 296..299

    __align__(16) __half2 hh[4];
    hh[0] = __floats2half2_rn(a.x, a.y);
    hh[1] = __floats2half2_rn(a.z, a.w);
    hh[2] = __floats2half2_rn(b.x, b.y);
    hh[3] = __floats2half2_rn(b.z, b.w);
    g_Wh4[i] = *reinterpret_cast<const int4*>(hh);
}

// ---------------------------------------------------------------------------
// Kernel 1: boundary-marking to build row_start from sorted sp_rows.
__global__ void build_row_ptr(const int* __restrict__ rows, int nnz, int batch) {
    int i = blockIdx.x * blockDim.x + threadIdx.x;
    if (i >= nnz) return;
    int r  = rows[i];
    int rp = (i == 0) ? -1 : rows[i - 1];
    for (int q = rp + 1; q <= r; ++q) g_row_start[q] = i;
    if (i == nnz - 1) {
        for (int q = r + 1; q <= batch; ++q) g_row_start[q] = nnz;
    }
}

// ---------------------------------------------------------------------------
// Kernel 2: one CTA (64 threads) per output row. Lanes t<38 each own 8 columns
// via one 16B gather per nnz. (col,val) pairs are loaded coalesced once per 32
// nnz and broadcast with shfl.
__global__ __launch_bounds__(64) void spmm_row_kernel(
    const int*   __restrict__ cols,
    const float* __restrict__ vals,
    const float* __restrict__ bias,
    float*       __restrict__ out)
{
    const int row  = blockIdx.x;
    const int t    = threadIdx.x;
    const int lane = t & 31;

    const int start = g_row_start[row];
    const int end   = g_row_start[row + 1];

    float acc[8] = {0.f, 0.f, 0.f, 0.f, 0.f, 0.f, 0.f, 0.f};
    const bool active = (t < 38);              // 38 * 8 = 304 >= 300 padded cols

    for (int base = start; base < end; base += 32) {
        const int rem = end - base;
        const int n   = rem < 32 ? rem : 32;
        int   c_l = 0;
        float v_l = 0.f;
        if (lane < n) {                        // coalesced batch load per warp
            c_l = __ldg(cols + base + lane);
            v_l = __ldg(vals + base + lane);
        }
        #pragma unroll 4
        for (int j = 0; j < n; ++j) {
            const int   c = __shfl_sync(0xffffffffu, c_l, j);
            const float v = __shfl_sync(0xffffffffu, v_l, j);
            if (active) {
                const int4 w4 = g_Wh4[c * ROW_INT4 + t];
                const __half2* wh = reinterpret_cast<const __half2*>(&w4);
                #pragma unroll
                for (int q = 0; q < 4; ++q) {
                    const float2 wf = __half22float2(wh[q]);
                    acc[2 * q]     = fmaf(v, wf.x, acc[2 * q]);
                    acc[2 * q + 1] = fmaf(v, wf.y, acc[2 * q + 1]);
                }
            }
        }
    }

    if (active) {
        const int col = t * 8;
        float* orow = out + (size_t)row * OUT_DIM + col;
        const float4 b0 = *reinterpret_cast<const float4*>(bias + col);
        float4 o0;
        o0.x = fmaxf(acc[0] + b0.x, 0.f);
        o0.y = fmaxf(acc[1] + b0.y, 0.f);
        o0.z = fmaxf(acc[2] + b0.z, 0.f);
        o0.w = fmaxf(acc[3] + b0.w, 0.f);
        *reinterpret_cast<float4*>(orow) = o0;
        if (t < 37) {                          // t==37 ends at col 299
            const float4 b1 = *reinterpret_cast<const float4*>(bias + col + 4);
            float4 o1;
            o1.x = fmaxf(acc[4] + b1.x, 0.f);
            o1.y = fmaxf(acc[5] + b1.y, 0.f);
            o1.z = fmaxf(acc[6] + b1.z, 0.f);
            o1.w = fmaxf(acc[7] + b1.w, 0.f);
            *reinterpret_cast<float4*>(orow + 4) = o1;
        }
    }
}

extern "C" void kernel_launch(void* const* d_in, const int* in_sizes, int n_in,
                              void* d_out, int out_size) {
    const int*   sp_rows = (const int*)  d_in[0];
    const int*   sp_cols = (const int*)  d_in[1];
    const float* sp_vals = (const float*)d_in[2];
    const float* weights = (const float*)d_in[3];
    const float* bias    = (const float*)d_in[4];

    const int nnz   = in_sizes[0];
    const int batch = out_size / OUT_DIM;

    convert_w<<<(IN_DIM * ROW_INT4 + 255) / 256, 256>>>(weights);
    build_row_ptr<<<(nnz + 255) / 256, 256>>>(sp_rows, nnz, batch);
    spmm_row_kernel<<<batch, 64>>>(sp_cols, sp_vals, bias, (float*)d_out);
}

// round 4
// speedup vs baseline: 1.6311x; 1.1971x over previous
#include <cuda_runtime.h>
#include <cuda_fp16.h>

// WordHashing: sparse [B=16384 x 30000] (COO, rows sorted) @ W [30000 x 300] + bias, ReLU.
// R3 post-mortem: spmm bound by warp-issue count (~42 issues/nnz across 2 warps,
// warp 1 mostly dead lanes). R4: ONE warp per row, 32 fully-active lanes
// (10 cols/lane via LDG.128 + LDG.32 on 320-col padded fp16 rows -> ~27 issues/nnz),
// and row bounds via per-warp binary search (build kernel eliminated).

#define OUT_DIM   300
#define IN_DIM    30000
#define ROW_INT4  40           // 40 x 16B = 640B per padded fp16 row (320 halves)
#define ROW_BYTES 640

__device__ __align__(128) int4 g_Wh4[IN_DIM * ROW_INT4];   // 19.2 MB fp16 staged weights

// ---------------------------------------------------------------------------
// Kernel 0: W f32 -> padded f16 rows (640B). Thread k of a row converts cols [8k, 8k+8).
__global__ void convert_w(const float* __restrict__ W) {
    const int i = blockIdx.x * blockDim.x + threadIdx.x;
    if (i >= IN_DIM * ROW_INT4) return;
    const int row = i / ROW_INT4;
    const int k   = i - row * ROW_INT4;
    const int col = k * 8;

    float4 a = make_float4(0.f, 0.f, 0.f, 0.f);
    float4 b = make_float4(0.f, 0.f, 0.f, 0.f);
    const float4* src = reinterpret_cast<const float4*>(W + (size_t)row * OUT_DIM + col);
    if (col + 8 <= OUT_DIM)      { a = src[0]; b = src[1]; }
    else if (col < OUT_DIM)      { a = src[0]; }           // col==296: cols 296..299

    __align__(16) __half2 hh[4];
    hh[0] = __floats2half2_rn(a.x, a.y);
    hh[1] = __floats2half2_rn(a.z, a.w);
    hh[2] = __floats2half2_rn(b.x, b.y);
    hh[3] = __floats2half2_rn(b.z, b.w);
    g_Wh4[i] = *reinterpret_cast<const int4*>(hh);
}

// ---------------------------------------------------------------------------
// Kernel 1: spmm. 128-thread CTA = 4 independent warps, one sparse row each.
// Lane t owns cols [8t, 8t+8) (LDG.128) and cols [256+2t, 256+2t+2) (LDG.32).
__global__ __launch_bounds__(128) void spmm_row_kernel(
    const int*   __restrict__ rows,   // sorted
    const int*   __restrict__ cols,
    const float* __restrict__ vals,
    const float* __restrict__ bias,
    float*       __restrict__ out,
    int nnz, int batch)
{
    const int warp = threadIdx.x >> 5;
    const int lane = threadIdx.x & 31;
    const int row  = blockIdx.x * 4 + warp;
    if (row >= batch) return;

    // Row bounds by binary search over sorted sp_rows.
    // Even lanes search lower_bound(row), odd lanes lower_bound(row+1).
    {
        const int target = row + (lane & 1);
        int lo = 0, hi = nnz;
        while (lo < hi) {
            const int mid = (lo + hi) >> 1;
            if (__ldg(rows + mid) < target) lo = mid + 1; else hi = mid;
        }
        // fallthrough: start from lane 0, end from lane 1
        const int start = __shfl_sync(0xffffffffu, lo, 0);
        const int end   = __shfl_sync(0xffffffffu, lo, 1);

        float acc[10] = {0.f,0.f,0.f,0.f,0.f,0.f,0.f,0.f,0.f,0.f};

        const char* __restrict__ wbase = reinterpret_cast<const char*>(g_Wh4);
        const int off128 = lane * 16;           // bytes into row, cols 8t..8t+7
        const int off32  = 512 + lane * 4;      // bytes into row, cols 256+2t

        for (int base = start; base < end; base += 32) {
            const int rem = end - base;
            const int n   = rem < 32 ? rem : 32;
            int   c_l = 0;
            float v_l = 0.f;
            if (lane < n) {
                c_l = __ldg(cols + base + lane);
                v_l = __ldg(vals + base + lane);
            }
            #pragma unroll 4
            for (int j = 0; j < n; ++j) {
                const int   c = __shfl_sync(0xffffffffu, c_l, j);
                const float v = __shfl_sync(0xffffffffu, v_l, j);
                const char* rowp = wbase + (size_t)c * ROW_BYTES;
                const int4 w4 = __ldg(reinterpret_cast<const int4*>(rowp + off128));
                const int  w1 = __ldg(reinterpret_cast<const int*>(rowp + off32));
                const __half2* wh = reinterpret_cast<const __half2*>(&w4);
                #pragma unroll
                for (int q = 0; q < 4; ++q) {
                    const float2 wf = __half22float2(wh[q]);
                    acc[2*q]   = fmaf(v, wf.x, acc[2*q]);
                    acc[2*q+1] = fmaf(v, wf.y, acc[2*q+1]);
                }
                const float2 wt = __half22float2(*reinterpret_cast<const __half2*>(&w1));
                acc[8] = fmaf(v, wt.x, acc[8]);
                acc[9] = fmaf(v, wt.y, acc[9]);
            }
        }

        // Epilogue: +bias, ReLU, coalesced stores.
        float* orow = out + (size_t)row * OUT_DIM;
        const int c0 = lane * 8;                 // 0..248, all < 300
        const float4 b0 = __ldg(reinterpret_cast<const float4*>(bias + c0));
        const float4 b1 = __ldg(reinterpret_cast<const float4*>(bias + c0 + 4));
        float4 o0, o1;
        o0.x = fmaxf(acc[0] + b0.x, 0.f);  o0.y = fmaxf(acc[1] + b0.y, 0.f);
        o0.z = fmaxf(acc[2] + b0.z, 0.f);  o0.w = fmaxf(acc[3] + b0.w, 0.f);
        o1.x = fmaxf(acc[4] + b1.x, 0.f);  o1.y = fmaxf(acc[5] + b1.y, 0.f);
        o1.z = fmaxf(acc[6] + b1.z, 0.f);  o1.w = fmaxf(acc[7] + b1.w, 0.f);
        *reinterpret_cast<float4*>(orow + c0)     = o0;
        *reinterpret_cast<float4*>(orow + c0 + 4) = o1;

        const int c1 = 256 + 2 * lane;           // 256..318; valid while < 300
        if (c1 < OUT_DIM) {                      // lanes 0..21
            const float2 b2 = __ldg(reinterpret_cast<const float2*>(bias + c1));
            float2 o2;
            o2.x = fmaxf(acc[8] + b2.x, 0.f);
            o2.y = fmaxf(acc[9] + b2.y, 0.f);
            *reinterpret_cast<float2*>(orow + c1) = o2;
        }
    }
}

extern "C" void kernel_launch(void* const* d_in, const int* in_sizes, int n_in,
                              void* d_out, int out_size) {
    const int*   sp_rows = (const int*)  d_in[0];
    const int*   sp_cols = (const int*)  d_in[1];
    const float* sp_vals = (const float*)d_in[2];
    const float* weights = (const float*)d_in[3];
    const float* bias    = (const float*)d_in[4];

    const int nnz   = in_sizes[0];
    const int batch = out_size / OUT_DIM;

    convert_w<<<(IN_DIM * ROW_INT4 + 255) / 256, 256>>>(weights);
    spmm_row_kernel<<<(batch + 3) / 4, 128>>>(sp_rows, sp_cols, sp_vals, bias,
                                              (float*)d_out, nnz, batch);
}

// round 5
// speedup vs baseline: 1.7449x; 1.0697x over previous
#include <cuda_runtime.h>
#include <cuda_fp16.h>

// WordHashing: sparse [B=16384 x 30000] (COO, rows sorted) @ W [30000 x 300] + bias, ReLU.
// R4 post-mortem: spmm issue/latency-bound (issue=51.9%, L2=34.7%, DRAM=7.9%).
// R5: (a) restore row_ptr kernel (kills 19-deep serial binary search per warp),
//     (b) packed fma.rn.f32x2 (5 FFMA2 instead of 10 FFMA),
//     (c) smem int2 (col,val) broadcast (1 LDS.64 instead of 2 SHFL),
//     (d) convert_w with 16 cols/thread for MLP.

#define OUT_DIM   300
#define IN_DIM    30000
#define ROW_INT4  40           // 40 x 16B = 640B per padded fp16 row (320 halves)
#define ROW_BYTES 640
#define MAX_BATCH 16384

__device__ int g_row_start[MAX_BATCH + 1];
__device__ __align__(128) int4 g_Wh4[IN_DIM * ROW_INT4];   // 19.2 MB fp16 staged weights

// ---------------------------------------------------------------------------
// Kernel 0: W f32 -> padded f16 rows (640B). Each thread converts 16 cols
// (4x float4 reads in flight, 2x int4 writes).
__global__ void convert_w(const float* __restrict__ W) {
    const int i = blockIdx.x * blockDim.x + threadIdx.x;     // [0, IN_DIM*20)
    if (i >= IN_DIM * 20) return;
    const int row = i / 20;
    const int col0 = (i - row * 20) * 16;                    // 0,16,...,304
    const float* src = W + (size_t)row * OUT_DIM + col0;

    float4 a[4];
    #pragma unroll
    for (int q = 0; q < 4; ++q) {
        const int col = col0 + 4 * q;
        a[q] = (col + 4 <= OUT_DIM) ? __ldg(reinterpret_cast<const float4*>(src + 4 * q))
                                    : make_float4(0.f, 0.f, 0.f, 0.f);
    }
    __align__(16) __half2 hh[8];
    #pragma unroll
    for (int q = 0; q < 4; ++q) {
        hh[2 * q]     = __floats2half2_rn(a[q].x, a[q].y);
        hh[2 * q + 1] = __floats2half2_rn(a[q].z, a[q].w);
    }
    const int4* p = reinterpret_cast<const int4*>(hh);
    g_Wh4[i * 2]     = p[0];
    g_Wh4[i * 2 + 1] = p[1];
}

// ---------------------------------------------------------------------------
// Kernel 1: boundary-marking to build row_start from sorted sp_rows.
__global__ void build_row_ptr(const int* __restrict__ rows, int nnz, int batch) {
    int i = blockIdx.x * blockDim.x + threadIdx.x;
    if (i >= nnz) return;
    int r  = rows[i];
    int rp = (i == 0) ? -1 : rows[i - 1];
    for (int q = rp + 1; q <= r; ++q) g_row_start[q] = i;
    if (i == nnz - 1) {
        for (int q = r + 1; q <= batch; ++q) g_row_start[q] = nnz;
    }
}

// ---------------------------------------------------------------------------
// Packed convert+FMA: acc(f32x2) += cvt(f16x2 w2) * vv(f32x2).
// The pair-forming mov.b64 ops are resolved by ptxas register allocation.
__device__ __forceinline__ void cvt_fma2(unsigned long long& acc,
                                         unsigned int w2,
                                         unsigned long long vv) {
    asm("{\n\t"
        ".reg .b16 l, h;\n\t"
        ".reg .f32 fl, fh;\n\t"
        ".reg .b64 wp;\n\t"
        "mov.b32 {l, h}, %1;\n\t"
        "cvt.f32.f16 fl, l;\n\t"
        "cvt.f32.f16 fh, h;\n\t"
        "mov.b64 wp, {fl, fh};\n\t"
        "fma.rn.f32x2 %0, wp, %2, %0;\n\t"
        "}" : "+l"(acc) : "r"(w2), "l"(vv));
}

// ---------------------------------------------------------------------------
// Kernel 2: spmm. 128-thread CTA = 4 independent warps, one sparse row each.
// Lane t owns cols [8t,8t+8) (LDG.128) + cols [256+2t,256+2t+2) (LDG.32).
__global__ __launch_bounds__(128) void spmm_row_kernel(
    const int*   __restrict__ cols,
    const float* __restrict__ vals,
    const float* __restrict__ bias,
    float*       __restrict__ out,
    int batch)
{
    __shared__ int2 s_cv[4][32];
    const int warp = threadIdx.x >> 5;
    const int lane = threadIdx.x & 31;
    const int row  = blockIdx.x * 4 + warp;
    if (row >= batch) return;

    const int start = g_row_start[row];      // uniform -> broadcast LDG
    const int end   = g_row_start[row + 1];

    unsigned long long a0 = 0ull, a1 = 0ull, a2 = 0ull, a3 = 0ull, a4 = 0ull;

    const char* __restrict__ wbase = reinterpret_cast<const char*>(g_Wh4);
    const int off128 = lane * 16;            // cols 8t..8t+7
    const int off32  = 512 + lane * 4;       // cols 256+2t

    for (int base = start; base < end; base += 32) {
        const int rem = end - base;
        const int n   = rem < 32 ? rem : 32;
        if (lane < n) {
            s_cv[warp][lane] = make_int2(__ldg(cols + base + lane),
                                         __float_as_int(__ldg(vals + base + lane)));
        }
        __syncwarp();
        #pragma unroll 8
        for (int j = 0; j < n; ++j) {
            const int2  cv = s_cv[warp][j];              // LDS.64 broadcast
            const float v  = __int_as_float(cv.y);
            unsigned long long vv;
            asm("mov.b64 %0, {%1, %1};" : "=l"(vv) : "f"(v));
            const char* rowp = wbase + (size_t)cv.x * ROW_BYTES;
            const int4 w4 = __ldg(reinterpret_cast<const int4*>(rowp + off128));
            const int  w1 = __ldg(reinterpret_cast<const int*>(rowp + off32));
            cvt_fma2(a0, (unsigned)w4.x, vv);
            cvt_fma2(a1, (unsigned)w4.y, vv);
            cvt_fma2(a2, (unsigned)w4.z, vv);
            cvt_fma2(a3, (unsigned)w4.w, vv);
            cvt_fma2(a4, (unsigned)w1,   vv);
        }
        __syncwarp();
    }

    // Unpack accumulators.
    float acc[10];
    asm("mov.b64 {%0, %1}, %2;" : "=f"(acc[0]), "=f"(acc[1]) : "l"(a0));
    asm("mov.b64 {%0, %1}, %2;" : "=f"(acc[2]), "=f"(acc[3]) : "l"(a1));
    asm("mov.b64 {%0, %1}, %2;" : "=f"(acc[4]), "=f"(acc[5]) : "l"(a2));
    asm("mov.b64 {%0, %1}, %2;" : "=f"(acc[6]), "=f"(acc[7]) : "l"(a3));
    asm("mov.b64 {%0, %1}, %2;" : "=f"(acc[8]), "=f"(acc[9]) : "l"(a4));

    // Epilogue: +bias, ReLU, coalesced stores.
    float* orow = out + (size_t)row * OUT_DIM;
    const int c0 = lane * 8;
    const float4 b0 = __ldg(reinterpret_cast<const float4*>(bias + c0));
    const float4 b1 = __ldg(reinterpret_cast<const float4*>(bias + c0 + 4));
    float4 o0, o1;
    o0.x = fmaxf(acc[0] + b0.x, 0.f);  o0.y = fmaxf(acc[1] + b0.y, 0.f);
    o0.z = fmaxf(acc[2] + b0.z, 0.f);  o0.w = fmaxf(acc[3] + b0.w, 0.f);
    o1.x = fmaxf(acc[4] + b1.x, 0.f);  o1.y = fmaxf(acc[5] + b1.y, 0.f);
    o1.z = fmaxf(acc[6] + b1.z, 0.f);  o1.w = fmaxf(acc[7] + b1.w, 0.f);
    *reinterpret_cast<float4*>(orow + c0)     = o0;
    *reinterpret_cast<float4*>(orow + c0 + 4) = o1;

    const int c1 = 256 + 2 * lane;
    if (c1 < OUT_DIM) {                        // lanes 0..21
        const float2 b2 = __ldg(reinterpret_cast<const float2*>(bias + c1));
        float2 o2;
        o2.x = fmaxf(acc[8] + b2.x, 0.f);
        o2.y = fmaxf(acc[9] + b2.y, 0.f);
        *reinterpret_cast<float2*>(orow + c1) = o2;
    }
}

extern "C" void kernel_launch(void* const* d_in, const int* in_sizes, int n_in,
                              void* d_out, int out_size) {
    const int*   sp_rows = (const int*)  d_in[0];
    const int*   sp_cols = (const int*)  d_in[1];
    const float* sp_vals = (const float*)d_in[2];
    const float* weights = (const float*)d_in[3];
    const float* bias    = (const float*)d_in[4];

    const int nnz   = in_sizes[0];
    const int batch = out_size / OUT_DIM;

    convert_w<<<(IN_DIM * 20 + 255) / 256, 256>>>(weights);
    build_row_ptr<<<(nnz + 255) / 256, 256>>>(sp_rows, nnz, batch);
    spmm_row_kernel<<<(batch + 3) / 4, 128>>>(sp_cols, sp_vals, bias,
                                              (float*)d_out, batch);
}

// round 6
// speedup vs baseline: 1.8336x; 1.0509x over previous
#include <cuda_runtime.h>
#include <cuda_fp16.h>

// WordHashing: sparse [B=16384 x 30000] (COO, rows sorted) @ W [30000 x 300] + bias, ReLU.
// R5 post-mortem: spmm ~27.5us sits on max(issue ~21/nnz, L2 640B/nnz) envelope.
// R6: 608B row stride (-5% L2 bytes, 3-sector tail read by 22 lanes only),
//     staged (c*608, val) pairs so the inner loop has no index multiply,
//     one syncwarp per chunk via double-buffered smem staging.

#define OUT_DIM   300
#define IN_DIM    30000
#define ROW_INT4  38           // 38 x 16B = 608B per padded fp16 row (304 halves)
#define ROW_BYTES 608
#define MAX_BATCH 16384

__device__ int g_row_start[MAX_BATCH + 1];
__device__ __align__(128) int4 g_Wh4[IN_DIM * ROW_INT4];   // 18.2 MB fp16 staged weights

// ---------------------------------------------------------------------------
// Kernel 0: W f32 -> padded f16 rows (608B). Thread k of a row converts cols [8k, 8k+8).
__global__ void convert_w(const float* __restrict__ W) {
    const int i = blockIdx.x * blockDim.x + threadIdx.x;
    if (i >= IN_DIM * ROW_INT4) return;
    const int row = i / ROW_INT4;
    const int k   = i - row * ROW_INT4;
    const int col = k * 8;

    float4 a = make_float4(0.f, 0.f, 0.f, 0.f);
    float4 b = make_float4(0.f, 0.f, 0.f, 0.f);
    const float4* src = reinterpret_cast<const float4*>(W + (size_t)row * OUT_DIM + col);
    if (col + 8 <= OUT_DIM)      { a = __ldg(src); b = __ldg(src + 1); }
    else if (col < OUT_DIM)      { a = __ldg(src); }       // k==37: cols 296..299

    __align__(16) __half2 hh[4];
    hh[0] = __floats2half2_rn(a.x, a.y);
    hh[1] = __floats2half2_rn(a.z, a.w);
    hh[2] = __floats2half2_rn(b.x, b.y);
    hh[3] = __floats2half2_rn(b.z, b.w);
    g_Wh4[i] = *reinterpret_cast<const int4*>(hh);
}

// ---------------------------------------------------------------------------
// Kernel 1: boundary-marking to build row_start from sorted sp_rows.
__global__ void build_row_ptr(const int* __restrict__ rows, int nnz, int batch) {
    int i = blockIdx.x * blockDim.x + threadIdx.x;
    if (i >= nnz) return;
    int r  = rows[i];
    int rp = (i == 0) ? -1 : rows[i - 1];
    for (int q = rp + 1; q <= r; ++q) g_row_start[q] = i;
    if (i == nnz - 1) {
        for (int q = r + 1; q <= batch; ++q) g_row_start[q] = nnz;
    }
}

// ---------------------------------------------------------------------------
// Packed convert+FMA: acc(f32x2) += cvt(f16x2 w2) * vv(f32x2).
__device__ __forceinline__ void cvt_fma2(unsigned long long& acc,
                                         unsigned int w2,
                                         unsigned long long vv) {
    asm("{\n\t"
        ".reg .b16 l, h;\n\t"
        ".reg .f32 fl, fh;\n\t"
        ".reg .b64 wp;\n\t"
        "mov.b32 {l, h}, %1;\n\t"
        "cvt.f32.f16 fl, l;\n\t"
        "cvt.f32.f16 fh, h;\n\t"
        "mov.b64 wp, {fl, fh};\n\t"
        "fma.rn.f32x2 %0, wp, %2, %0;\n\t"
        "}" : "+l"(acc) : "r"(w2), "l"(vv));
}

// ---------------------------------------------------------------------------
// Kernel 2: spmm. 128-thread CTA = 4 independent warps, one sparse row each.
// Lane t owns cols [8t,8t+8) (LDG.128); lanes 0..21 also own cols [256+2t,+2) (LDG.32).
// smem stages (c*ROW_BYTES, val) pairs, double-buffered (one syncwarp per chunk).
__global__ __launch_bounds__(128) void spmm_row_kernel(
    const int*   __restrict__ cols,
    const float* __restrict__ vals,
    const float* __restrict__ bias,
    float*       __restrict__ out,
    int batch)
{
    __shared__ int2 s_cv[4][2][32];
    const int warp = threadIdx.x >> 5;
    const int lane = threadIdx.x & 31;
    const int row  = blockIdx.x * 4 + warp;
    if (row >= batch) return;

    const int start = g_row_start[row];        // uniform -> broadcast LDG
    const int end   = g_row_start[row + 1];

    unsigned long long a0 = 0ull, a1 = 0ull, a2 = 0ull, a3 = 0ull, a4 = 0ull;

    // Per-lane base: gather address = lbase + staged_row_offset (+imm for tail).
    const char* __restrict__ lbase =
        reinterpret_cast<const char*>(g_Wh4) + lane * 16;
    const int tail_imm = 512 - lane * 16 + lane * 4;   // rowp+512+4*lane relative to lbase
    const bool has_tail = (lane < 22);

    int parity = 0;
    for (int base = start; base < end; base += 32, parity ^= 1) {
        const int rem = end - base;
        const int n   = rem < 32 ? rem : 32;
        if (lane < n) {
            s_cv[warp][parity][lane] =
                make_int2(__ldg(cols + base + lane) * ROW_BYTES,
                          __float_as_int(__ldg(vals + base + lane)));
        }
        __syncwarp();
        #pragma unroll 8
        for (int j = 0; j < n; ++j) {
            const int2  cv = s_cv[warp][parity][j];    // LDS.64 broadcast
            const float v  = __int_as_float(cv.y);
            unsigned long long vv;
            asm("mov.b64 %0, {%1, %1};" : "=l"(vv) : "f"(v));
            const char* p = lbase + cv.x;
            const int4 w4 = __ldg(reinterpret_cast<const int4*>(p));
            int w1 = 0;
            if (has_tail) w1 = __ldg(reinterpret_cast<const int*>(p + tail_imm));
            cvt_fma2(a0, (unsigned)w4.x, vv);
            cvt_fma2(a1, (unsigned)w4.y, vv);
            cvt_fma2(a2, (unsigned)w4.z, vv);
            cvt_fma2(a3, (unsigned)w4.w, vv);
            cvt_fma2(a4, (unsigned)w1,   vv);
        }
    }

    float acc[10];
    asm("mov.b64 {%0, %1}, %2;" : "=f"(acc[0]), "=f"(acc[1]) : "l"(a0));
    asm("mov.b64 {%0, %1}, %2;" : "=f"(acc[2]), "=f"(acc[3]) : "l"(a1));
    asm("mov.b64 {%0, %1}, %2;" : "=f"(acc[4]), "=f"(acc[5]) : "l"(a2));
    asm("mov.b64 {%0, %1}, %2;" : "=f"(acc[6]), "=f"(acc[7]) : "l"(a3));
    asm("mov.b64 {%0, %1}, %2;" : "=f"(acc[8]), "=f"(acc[9]) : "l"(a4));

    // Epilogue: +bias, ReLU, coalesced stores.
    float* orow = out + (size_t)row * OUT_DIM;
    const int c0 = lane * 8;
    const float4 b0 = __ldg(reinterpret_cast<const float4*>(bias + c0));
    const float4 b1 = __ldg(reinterpret_cast<const float4*>(bias + c0 + 4));
    float4 o0, o1;
    o0.x = fmaxf(acc[0] + b0.x, 0.f);  o0.y = fmaxf(acc[1] + b0.y, 0.f);
    o0.z = fmaxf(acc[2] + b0.z, 0.f);  o0.w = fmaxf(acc[3] + b0.w, 0.f);
    o1.x = fmaxf(acc[4] + b1.x, 0.f);  o1.y = fmaxf(acc[5] + b1.y, 0.f);
    o1.z = fmaxf(acc[6] + b1.z, 0.f);  o1.w = fmaxf(acc[7] + b1.w, 0.f);
    *reinterpret_cast<float4*>(orow + c0)     = o0;
    *reinterpret_cast<float4*>(orow + c0 + 4) = o1;

    const int c1 = 256 + 2 * lane;
    if (c1 < OUT_DIM) {                         // lanes 0..21
        const float2 b2 = __ldg(reinterpret_cast<const float2*>(bias + c1));
        float2 o2;
        o2.x = fmaxf(acc[8] + b2.x, 0.f);
        o2.y = fmaxf(acc[9] + b2.y, 0.f);
        *reinterpret_cast<float2*>(orow + c1) = o2;
    }
}

extern "C" void kernel_launch(void* const* d_in, const int* in_sizes, int n_in,
                              void* d_out, int out_size) {
    const int*   sp_rows = (const int*)  d_in[0];
    const int*   sp_cols = (const int*)  d_in[1];
    const float* sp_vals = (const float*)d_in[2];
    const float* weights = (const float*)d_in[3];
    const float* bias    = (const float*)d_in[4];

    const int nnz   = in_sizes[0];
    const int batch = out_size / OUT_DIM;

    convert_w<<<(IN_DIM * ROW_INT4 + 255) / 256, 256>>>(weights);
    build_row_ptr<<<(nnz + 255) / 256, 256>>>(sp_rows, nnz, batch);
    spmm_row_kernel<<<(batch + 3) / 4, 128>>>(sp_cols, sp_vals, bias,
                                              (float*)d_out, batch);
}

// round 7
// speedup vs baseline: 1.9266x; 1.0507x over previous
#include <cuda_runtime.h>
#include <cuda_fp16.h>

// WordHashing: sparse [B=16384 x 30000] (COO, rows sorted) @ W [30000 x 300] + bias, ReLU.
// R6 post-mortem: spmm (~26us) is pinned at the LTS chip cap (~13 TB/s through L2)
// with minimal bytes (608B/nnz); issue count no longer binding. Remaining slack is
// prep serialization. R7: fuse convert_w + build_row_ptr into ONE launch
// (block-range split; independent outputs), and prefetch the next (col,val)
// chunk in spmm to hide per-chunk LDG latency.

#define OUT_DIM   300
#define IN_DIM    30000
#define ROW_INT4  38           // 38 x 16B = 608B per padded fp16 row (304 halves)
#define ROW_BYTES 608
#define MAX_BATCH 16384

#define CONV_THREADS 256
#define CONV_BLOCKS  ((IN_DIM * ROW_INT4 + CONV_THREADS - 1) / CONV_THREADS)   // 4454

__device__ int g_row_start[MAX_BATCH + 1];
__device__ __align__(128) int4 g_Wh4[IN_DIM * ROW_INT4];   // 18.2 MB fp16 staged weights

// ---------------------------------------------------------------------------
// Fused prep kernel: blocks [0, CONV_BLOCKS) convert W f32 -> padded f16 rows;
// blocks >= CONV_BLOCKS build row_start from sorted sp_rows. Outputs disjoint.
__global__ void prep_kernel(const float* __restrict__ W,
                            const int* __restrict__ rows,
                            int nnz, int batch, int build_blocks_thr) {
    if (blockIdx.x < (unsigned)build_blocks_thr) {
        // ---- convert part ----
        const int i = blockIdx.x * CONV_THREADS + threadIdx.x;
        if (i >= IN_DIM * ROW_INT4) return;
        const int row = i / ROW_INT4;
        const int k   = i - row * ROW_INT4;
        const int col = k * 8;

        float4 a = make_float4(0.f, 0.f, 0.f, 0.f);
        float4 b = make_float4(0.f, 0.f, 0.f, 0.f);
        const float4* src = reinterpret_cast<const float4*>(W + (size_t)row * OUT_DIM + col);
        if (col + 8 <= OUT_DIM)      { a = __ldg(src); b = __ldg(src + 1); }
        else if (col < OUT_DIM)      { a = __ldg(src); }   // k==37: cols 296..299

        __align__(16) __half2 hh[4];
        hh[0] = __floats2half2_rn(a.x, a.y);
        hh[1] = __floats2half2_rn(a.z, a.w);
        hh[2] = __floats2half2_rn(b.x, b.y);
        hh[3] = __floats2half2_rn(b.z, b.w);
        g_Wh4[i] = *reinterpret_cast<const int4*>(hh);
    } else {
        // ---- row_ptr part (boundary marking) ----
        const int i = (blockIdx.x - build_blocks_thr) * CONV_THREADS + threadIdx.x;
        if (i >= nnz) return;
        int r  = rows[i];
        int rp = (i == 0) ? -1 : rows[i - 1];
        for (int q = rp + 1; q <= r; ++q) g_row_start[q] = i;
        if (i == nnz - 1) {
            for (int q = r + 1; q <= batch; ++q) g_row_start[q] = nnz;
        }
    }
}

// ---------------------------------------------------------------------------
// Packed convert+FMA: acc(f32x2) += cvt(f16x2 w2) * vv(f32x2).
__device__ __forceinline__ void cvt_fma2(unsigned long long& acc,
                                         unsigned int w2,
                                         unsigned long long vv) {
    asm("{\n\t"
        ".reg .b16 l, h;\n\t"
        ".reg .f32 fl, fh;\n\t"
        ".reg .b64 wp;\n\t"
        "mov.b32 {l, h}, %1;\n\t"
        "cvt.f32.f16 fl, l;\n\t"
        "cvt.f32.f16 fh, h;\n\t"
        "mov.b64 wp, {fl, fh};\n\t"
        "fma.rn.f32x2 %0, wp, %2, %0;\n\t"
        "}" : "+l"(acc) : "r"(w2), "l"(vv));
}

// ---------------------------------------------------------------------------
// spmm: 128-thread CTA = 4 independent warps, one sparse row each.
// Lane t owns cols [8t,8t+8) (LDG.128); lanes 0..21 also own cols [256+2t,+2) (LDG.32).
// (col,val) chunks staged via smem, register-prefetched one chunk ahead.
__global__ __launch_bounds__(128) void spmm_row_kernel(
    const int*   __restrict__ cols,
    const float* __restrict__ vals,
    const float* __restrict__ bias,
    float*       __restrict__ out,
    int batch)
{
    __shared__ int2 s_cv[4][2][32];
    const int warp = threadIdx.x >> 5;
    const int lane = threadIdx.x & 31;
    const int row  = blockIdx.x * 4 + warp;
    if (row >= batch) return;

    const int start = g_row_start[row];        // uniform -> broadcast LDG
    const int end   = g_row_start[row + 1];

    unsigned long long a0 = 0ull, a1 = 0ull, a2 = 0ull, a3 = 0ull, a4 = 0ull;

    const char* __restrict__ lbase =
        reinterpret_cast<const char*>(g_Wh4) + lane * 16;
    const int tail_imm = 512 - lane * 16 + lane * 4;   // rowp+512+4*lane rel. to lbase
    const bool has_tail = (lane < 22);

    // Prefetch chunk 0 into registers.
    int2 pf = make_int2(0, 0);
    if (start + lane < end) {
        pf = make_int2(__ldg(cols + start + lane) * ROW_BYTES,
                       __float_as_int(__ldg(vals + start + lane)));
    }

    int parity = 0;
    for (int base = start; base < end; base += 32, parity ^= 1) {
        const int rem = end - base;
        const int n   = rem < 32 ? rem : 32;
        s_cv[warp][parity][lane] = pf;         // publish current chunk
        __syncwarp();
        // Prefetch next chunk while current is processed.
        const int nb = base + 32;
        if (nb + lane < end) {
            pf = make_int2(__ldg(cols + nb + lane) * ROW_BYTES,
                           __float_as_int(__ldg(vals + nb + lane)));
        }
        #pragma unroll 8
        for (int j = 0; j < n; ++j) {
            const int2  cv = s_cv[warp][parity][j];    // LDS.64 broadcast
            const float v  = __int_as_float(cv.y);
            unsigned long long vv;
            asm("mov.b64 %0, {%1, %1};" : "=l"(vv) : "f"(v));
            const char* p = lbase + cv.x;
            const int4 w4 = __ldg(reinterpret_cast<const int4*>(p));
            int w1 = 0;
            if (has_tail) w1 = __ldg(reinterpret_cast<const int*>(p + tail_imm));
            cvt_fma2(a0, (unsigned)w4.x, vv);
            cvt_fma2(a1, (unsigned)w4.y, vv);
            cvt_fma2(a2, (unsigned)w4.z, vv);
            cvt_fma2(a3, (unsigned)w4.w, vv);
            cvt_fma2(a4, (unsigned)w1,   vv);
        }
    }

    float acc[10];
    asm("mov.b64 {%0, %1}, %2;" : "=f"(acc[0]), "=f"(acc[1]) : "l"(a0));
    asm("mov.b64 {%0, %1}, %2;" : "=f"(acc[2]), "=f"(acc[3]) : "l"(a1));
    asm("mov.b64 {%0, %1}, %2;" : "=f"(acc[4]), "=f"(acc[5]) : "l"(a2));
    asm("mov.b64 {%0, %1}, %2;" : "=f"(acc[6]), "=f"(acc[7]) : "l"(a3));
    asm("mov.b64 {%0, %1}, %2;" : "=f"(acc[8]), "=f"(acc[9]) : "l"(a4));

    // Epilogue: +bias, ReLU, coalesced stores.
    float* orow = out + (size_t)row * OUT_DIM;
    const int c0 = lane * 8;
    const float4 b0 = __ldg(reinterpret_cast<const float4*>(bias + c0));
    const float4 b1 = __ldg(reinterpret_cast<const float4*>(bias + c0 + 4));
    float4 o0, o1;
    o0.x = fmaxf(acc[0] + b0.x, 0.f);  o0.y = fmaxf(acc[1] + b0.y, 0.f);
    o0.z = fmaxf(acc[2] + b0.z, 0.f);  o0.w = fmaxf(acc[3] + b0.w, 0.f);
    o1.x = fmaxf(acc[4] + b1.x, 0.f);  o1.y = fmaxf(acc[5] + b1.y, 0.f);
    o1.z = fmaxf(acc[6] + b1.z, 0.f);  o1.w = fmaxf(acc[7] + b1.w, 0.f);
    *reinterpret_cast<float4*>(orow + c0)     = o0;
    *reinterpret_cast<float4*>(orow + c0 + 4) = o1;

    const int c1 = 256 + 2 * lane;
    if (c1 < OUT_DIM) {                         // lanes 0..21
        const float2 b2 = __ldg(reinterpret_cast<const float2*>(bias + c1));
        float2 o2;
        o2.x = fmaxf(acc[8] + b2.x, 0.f);
        o2.y = fmaxf(acc[9] + b2.y, 0.f);
        *reinterpret_cast<float2*>(orow + c1) = o2;
    }
}

extern "C" void kernel_launch(void* const* d_in, const int* in_sizes, int n_in,
                              void* d_out, int out_size) {
    const int*   sp_rows = (const int*)  d_in[0];
    const int*   sp_cols = (const int*)  d_in[1];
    const float* sp_vals = (const float*)d_in[2];
    const float* weights = (const float*)d_in[3];
    const float* bias    = (const float*)d_in[4];

    const int nnz   = in_sizes[0];
    const int batch = out_size / OUT_DIM;

    const int build_blocks = (nnz + CONV_THREADS - 1) / CONV_THREADS;
    prep_kernel<<<CONV_BLOCKS + build_blocks, CONV_THREADS>>>(
        weights, sp_rows, nnz, batch, CONV_BLOCKS);
    spmm_row_kernel<<<(batch + 3) / 4, 128>>>(sp_cols, sp_vals, bias,
                                              (float*)d_out, batch);
}